// round 8
// baseline (speedup 1.0000x reference)
#include <cuda_runtime.h>
#include <cstdint>

// DiagLinear fused: y[m, n*16+p] = sum_k x[m, p*256+k] * w[p, n, k] + bias[n*16+p]
// P=16, DIN=DOUT=256, M=16384.
//
// Single kernel: per-partition TF32 GEMM via mma.sync.m16n8k8 (legacy HMMA;
// tcgen05 not available at .target sm_103). CTA 256 thr, tile M=128 x N=128,
// KC=32 x 8 chunks, DOUBLE-buffered smem (64KB -> 2 CTAs/SM), cvt.rna at STS.
// Direct interleaved stores: 16 partition-partner CTAs are consecutive bids,
// so their 4B-strided writes merge into full lines in L2.

#define P_PART 16
#define DIN    256
#define DOUT   256
#define KC     32
#define NCHUNK 8

#define ABUF_BYTES 16384            // 128 rows x 128B
#define BBUF_BYTES 16384            // 128 rows x 128B
#define SMEM_B_OFF (2 * ABUF_BYTES) // 32768
#define SMEM_BIAS  (SMEM_B_OFF + 2 * BBUF_BYTES)  // 65536
#define GEMM_SMEM  (SMEM_BIAS + 512 + 64)         // 66112

static __device__ __forceinline__ uint32_t smem_u32(const void* p) {
    uint32_t a;
    asm("{ .reg .u64 t; cvta.to.shared.u64 t, %1; cvt.u32.u64 %0, t; }" : "=r"(a) : "l"(p));
    return a;
}

static __device__ __forceinline__ uint32_t f2tf32(float v) {
    uint32_t u;
    asm("cvt.rna.tf32.f32 %0, %1;" : "=r"(u) : "f"(v));
    return u;
}

__global__ __launch_bounds__(256, 2)
void diag_gemm_fused(const float* __restrict__ x, const float* __restrict__ w,
                     const float* __restrict__ bias, float* __restrict__ y)
{
    extern __shared__ char smem[];
    const int tid  = threadIdx.x;
    const int wid  = tid >> 5;
    const int lane = tid & 31;

    // grid.x = 32: p fastest (write-line partners adjacent), then n-half
    const int p     = blockIdx.x & 15;
    const int nhalf = blockIdx.x >> 4;
    const int n0    = nhalf * 128;
    const int m0    = blockIdx.y * 128;

    const int warp_m = wid & 3;             // 0..3 -> 32 rows
    const int warp_n = wid >> 2;            // 0..1 -> 64 cols

    const float* xbase = x + (size_t)m0 * (P_PART * DIN) + (size_t)p * DIN;
    const float* wbase = w + (size_t)p * (DOUT * DIN) + (size_t)n0 * DIN;

    // ---- bias slice: bias_s[i] = bias[(n0+i)*16 + p] ----
    {
        float* bias_s = reinterpret_cast<float*>(smem + SMEM_BIAS);
        if (tid < 128) bias_s[tid] = bias[(n0 + tid) * P_PART + p];
    }

    // ---- per-lane ldmatrix address precompute ----
    const int g  = lane >> 3;
    const int l8 = lane & 7;
    const int rowA = warp_m * 32 + (g & 1) * 8 + l8;
    const int cA   = g >> 1;
    const int rowB = warp_n * 64 + (g >> 1) * 8 + l8;
    const int cB   = g & 1;

    const uint32_t sbase  = smem_u32(smem);
    const uint32_t aAddr0 = sbase + rowA * 128;
    const uint32_t bAddr0 = sbase + SMEM_B_OFF + rowB * 128;
    const int swA = rowA & 7, swB = rowB & 7;

    float acc[2][8][4];
#pragma unroll
    for (int mm = 0; mm < 2; mm++)
#pragma unroll
        for (int nn = 0; nn < 8; nn++)
#pragma unroll
            for (int c = 0; c < 4; c++) acc[mm][nn][c] = 0.0f;

    float4 ra[4], rb[4];

#define LDG_AB(KCI)                                                             \
    _Pragma("unroll")                                                           \
    for (int i = 0; i < 4; i++) {                                               \
        int idx = i * 256 + tid;                                                \
        ra[i] = *reinterpret_cast<const float4*>(                               \
            xbase + (size_t)(idx >> 3) * (P_PART * DIN) + (KCI) * KC + (idx & 7) * 4); \
        rb[i] = *reinterpret_cast<const float4*>(                               \
            wbase + (size_t)(idx >> 3) * DIN + (KCI) * KC + (idx & 7) * 4);     \
    }

#define STS_AB(BUF)                                                             \
    _Pragma("unroll")                                                           \
    for (int i = 0; i < 4; i++) {                                               \
        int idx = i * 256 + tid;                                                \
        int row = idx >> 3, q = idx & 7;                                        \
        uint32_t so = row * 128 + ((q ^ (row & 7)) << 4);                       \
        *reinterpret_cast<uint4*>(smem + (BUF) * ABUF_BYTES + so) =             \
            make_uint4(f2tf32(ra[i].x), f2tf32(ra[i].y),                        \
                       f2tf32(ra[i].z), f2tf32(ra[i].w));                       \
        *reinterpret_cast<uint4*>(smem + SMEM_B_OFF + (BUF) * BBUF_BYTES + so) =\
            make_uint4(f2tf32(rb[i].x), f2tf32(rb[i].y),                        \
                       f2tf32(rb[i].z), f2tf32(rb[i].w));                       \
    }

#define COMPUTE(BUF)                                                            \
    {                                                                           \
        const uint32_t abase = aAddr0 + (BUF) * ABUF_BYTES;                     \
        const uint32_t bbase = bAddr0 + (BUF) * BBUF_BYTES;                     \
        _Pragma("unroll")                                                       \
        for (int ks = 0; ks < 4; ks++) {                                        \
            const int cb = ks * 2;                                              \
            uint32_t a[2][4], b[4][4];                                          \
            _Pragma("unroll")                                                   \
            for (int mm = 0; mm < 2; mm++) {                                    \
                uint32_t ad = abase + mm * 2048 + (((cb + cA) ^ swA) << 4);     \
                asm volatile(                                                   \
                    "ldmatrix.sync.aligned.m8n8.x4.shared.b16 {%0,%1,%2,%3}, [%4];" \
                    : "=r"(a[mm][0]), "=r"(a[mm][1]), "=r"(a[mm][2]), "=r"(a[mm][3]) \
                    : "r"(ad));                                                 \
            }                                                                   \
            _Pragma("unroll")                                                   \
            for (int q = 0; q < 4; q++) {                                       \
                uint32_t bd = bbase + q * 2048 + (((cb + cB) ^ swB) << 4);      \
                asm volatile(                                                   \
                    "ldmatrix.sync.aligned.m8n8.x4.shared.b16 {%0,%1,%2,%3}, [%4];" \
                    : "=r"(b[q][0]), "=r"(b[q][1]), "=r"(b[q][2]), "=r"(b[q][3]) \
                    : "r"(bd));                                                 \
            }                                                                   \
            _Pragma("unroll")                                                   \
            for (int mm = 0; mm < 2; mm++)                                      \
                _Pragma("unroll")                                               \
                for (int nn = 0; nn < 8; nn++) {                                \
                    asm volatile(                                               \
                        "mma.sync.aligned.m16n8k8.row.col.f32.tf32.tf32.f32 "   \
                        "{%0,%1,%2,%3}, {%4,%5,%6,%7}, {%8,%9}, {%0,%1,%2,%3};" \
                        : "+f"(acc[mm][nn][0]), "+f"(acc[mm][nn][1]),           \
                          "+f"(acc[mm][nn][2]), "+f"(acc[mm][nn][3])            \
                        : "r"(a[mm][0]), "r"(a[mm][1]), "r"(a[mm][2]), "r"(a[mm][3]), \
                          "r"(b[nn >> 1][(nn & 1) * 2]), "r"(b[nn >> 1][(nn & 1) * 2 + 1])); \
                }                                                               \
        }                                                                       \
    }

    // ---- prologue: chunk 0 in smem, chunk 1 in regs ----
    LDG_AB(0);
    STS_AB(0);
    LDG_AB(1);
    __syncthreads();

    // ---- main loop: 1 sync/iter, double buffer, distance-2 reg prefetch ----
    // iter kc: STS(kc+1) [regs from last iter] -> buf (kc+1)&1 (safe: its last
    // reader, COMPUTE(kc-1), finished at previous sync); LDG(kc+2) -> regs;
    // COMPUTE(kc) on buf kc&1 (no conflict with STS target); sync.
#pragma unroll 1
    for (int kc = 0; kc < NCHUNK; kc++) {
        if (kc + 1 < NCHUNK) { STS_AB((kc + 1) & 1); }
        if (kc + 2 < NCHUNK) { LDG_AB(kc + 2); }
        COMPUTE(kc & 1);
        __syncthreads();
    }

    // ---- epilogue: direct interleaved stores + bias ----
    {
        const float* bias_s = reinterpret_cast<const float*>(smem + SMEM_BIAS);
        const int r0 = lane >> 2;
        const int c0 = (lane & 3) * 2;
#pragma unroll
        for (int mm = 0; mm < 2; mm++) {
            const int mr = m0 + warp_m * 32 + mm * 16 + r0;
            float* yr0 = y + (size_t)mr * (DOUT * P_PART) + p;
            float* yr1 = yr0 + 8 * (DOUT * P_PART);
#pragma unroll
            for (int nn = 0; nn < 8; nn++) {
                const int nl = warp_n * 64 + nn * 8 + c0;   // local n in [0,128)
                const float b0 = bias_s[nl], b1 = bias_s[nl + 1];
                const size_t o0 = (size_t)(n0 + nl) * P_PART;
                yr0[o0]          = acc[mm][nn][0] + b0;
                yr0[o0 + P_PART] = acc[mm][nn][1] + b1;
                yr1[o0]          = acc[mm][nn][2] + b0;
                yr1[o0 + P_PART] = acc[mm][nn][3] + b1;
            }
        }
    }
}

extern "C" void kernel_launch(void* const* d_in, const int* in_sizes, int n_in,
                              void* d_out, int out_size)
{
    const float* x    = (const float*)d_in[0];
    const float* w    = (const float*)d_in[1];
    const float* bias = (const float*)d_in[2];
    float* y = (float*)d_out;

    int M = in_sizes[0] / (P_PART * DIN);      // 16384

    cudaFuncSetAttribute(diag_gemm_fused,
                         cudaFuncAttributeMaxDynamicSharedMemorySize, GEMM_SMEM);

    dim3 grid(32, M / 128);                    // x: p(16) * nhalf(2), p fastest
    diag_gemm_fused<<<grid, 256, GEMM_SMEM>>>(x, w, bias, y);
}

// round 9
// speedup vs baseline: 1.0225x; 1.0225x over previous
#include <cuda_runtime.h>
#include <cstdint>

// DiagLinear fused: y[m, n*16+p] = sum_k x[m, p*256+k] * w[p, n, k] + bias[n*16+p]
// P=16, DIN=DOUT=256, M=16384.
//
// TF32 mma.sync GEMM, cp.async 4-stage pipeline (no register staging -> no
// spill), CTA 512thr, tile M=128 x N=256 (X read from DRAM once), KC=32 x 8.
// Raw fp32 in smem; HMMA's own fp32->tf32 conversion (accuracy probe).
// Direct interleaved stores; 16 partition-partner CTAs adjacent in grid so
// 4B-strided writes merge to full lines in L2 (DRAM writes stay 256MB).

#define P_PART 16
#define DIN    256
#define DOUT   256
#define KC     32
#define NCHUNK 8
#define STAGES 4

#define ABUF_BYTES 16384                    // 128 rows x 128B
#define BBUF_BYTES 32768                    // 256 rows x 128B
#define SMEM_B_OFF (STAGES * ABUF_BYTES)    // 65536
#define SMEM_BIAS  (SMEM_B_OFF + STAGES * BBUF_BYTES)   // 196608
#define GEMM_SMEM  (SMEM_BIAS + 1024)       // 197632

static __device__ __forceinline__ uint32_t smem_u32(const void* p) {
    uint32_t a;
    asm("{ .reg .u64 t; cvta.to.shared.u64 t, %1; cvt.u32.u64 %0, t; }" : "=r"(a) : "l"(p));
    return a;
}

static __device__ __forceinline__ void cp_async16(uint32_t dst, const void* src) {
    asm volatile("cp.async.cg.shared.global [%0], [%1], 16;" :: "r"(dst), "l"(src));
}

__global__ __launch_bounds__(512, 1)
void diag_gemm_fused(const float* __restrict__ x, const float* __restrict__ w,
                     const float* __restrict__ bias, float* __restrict__ y)
{
    extern __shared__ char smem[];
    const int tid  = threadIdx.x;
    const int wid  = tid >> 5;
    const int lane = tid & 31;

    const int p  = blockIdx.x;              // p fastest -> L2 write-merge partners
    const int m0 = blockIdx.y * 128;

    const int warp_m = wid >> 2;            // 0..3 -> 32 rows
    const int warp_n = wid & 3;             // 0..3 -> 64 cols

    const float* xbase = x + (size_t)m0 * (P_PART * DIN) + (size_t)p * DIN;
    const float* wbase = w + (size_t)p * (DOUT * DIN);

    const uint32_t sbase = smem_u32(smem);

    // bias_s[n] = bias[n*16+p]
    {
        float* bias_s = reinterpret_cast<float*>(smem + SMEM_BIAS);
        if (tid < 256) bias_s[tid] = bias[tid * P_PART + p];
    }

    // ---- per-lane ldmatrix addresses ----
    const int g  = lane >> 3;
    const int l8 = lane & 7;
    const int rowA = warp_m * 32 + (g & 1) * 8 + l8;
    const int cA   = g >> 1;
    const int rowB = warp_n * 64 + (g >> 1) * 8 + l8;
    const int cB   = g & 1;

    const uint32_t aAddr0 = sbase + rowA * 128;
    const uint32_t bAddr0 = sbase + SMEM_B_OFF + rowB * 128;
    const int swA = rowA & 7, swB = rowB & 7;

    // ---- per-thread cp.async src/dst precompute ----
    // A: 1024 x 16B, 2 per thread; B: 2048 x 16B, 4 per thread
    const int rA0 = tid >> 3, qA = tid & 7;                 // rows tid>>3, +64
    const uint32_t dA0 = sbase + rA0 * 128 + ((qA ^ (rA0 & 7)) << 4);
    const uint32_t dA1 = sbase + (rA0 + 64) * 128 + ((qA ^ ((rA0 + 64) & 7)) << 4);
    const float* sA0 = xbase + (size_t)rA0 * (P_PART * DIN) + qA * 4;
    const float* sA1 = xbase + (size_t)(rA0 + 64) * (P_PART * DIN) + qA * 4;

#define ISSUE_STAGE(KCI, ST)                                                    \
    {                                                                           \
        const int kofs = (KCI) * KC;                                            \
        cp_async16(dA0 + (ST) * ABUF_BYTES, sA0 + kofs);                        \
        cp_async16(dA1 + (ST) * ABUF_BYTES, sA1 + kofs);                        \
        _Pragma("unroll")                                                       \
        for (int i = 0; i < 4; i++) {                                           \
            int idx = i * 512 + tid;                                            \
            int row = idx >> 3, q = idx & 7;                                    \
            uint32_t dst = sbase + SMEM_B_OFF + (ST) * BBUF_BYTES               \
                         + row * 128 + ((q ^ (row & 7)) << 4);                  \
            cp_async16(dst, wbase + (size_t)row * DIN + kofs + q * 4);          \
        }                                                                       \
        asm volatile("cp.async.commit_group;" ::: "memory");                    \
    }

    float acc[2][8][4];
#pragma unroll
    for (int mm = 0; mm < 2; mm++)
#pragma unroll
        for (int nn = 0; nn < 8; nn++)
#pragma unroll
            for (int c = 0; c < 4; c++) acc[mm][nn][c] = 0.0f;

#define COMPUTE(BUF)                                                            \
    {                                                                           \
        const uint32_t abase = aAddr0 + (BUF) * ABUF_BYTES;                     \
        const uint32_t bbase = bAddr0 + (BUF) * BBUF_BYTES;                     \
        _Pragma("unroll")                                                       \
        for (int ks = 0; ks < 4; ks++) {                                        \
            const int cb = ks * 2;                                              \
            uint32_t a[2][4], b[4][4];                                          \
            _Pragma("unroll")                                                   \
            for (int mm = 0; mm < 2; mm++) {                                    \
                uint32_t ad = abase + mm * 2048 + (((cb + cA) ^ swA) << 4);     \
                asm volatile(                                                   \
                    "ldmatrix.sync.aligned.m8n8.x4.shared.b16 {%0,%1,%2,%3}, [%4];" \
                    : "=r"(a[mm][0]), "=r"(a[mm][1]), "=r"(a[mm][2]), "=r"(a[mm][3]) \
                    : "r"(ad));                                                 \
            }                                                                   \
            _Pragma("unroll")                                                   \
            for (int q = 0; q < 4; q++) {                                       \
                uint32_t bd = bbase + q * 2048 + (((cb + cB) ^ swB) << 4);      \
                asm volatile(                                                   \
                    "ldmatrix.sync.aligned.m8n8.x4.shared.b16 {%0,%1,%2,%3}, [%4];" \
                    : "=r"(b[q][0]), "=r"(b[q][1]), "=r"(b[q][2]), "=r"(b[q][3]) \
                    : "r"(bd));                                                 \
            }                                                                   \
            _Pragma("unroll")                                                   \
            for (int mm = 0; mm < 2; mm++)                                      \
                _Pragma("unroll")                                               \
                for (int nn = 0; nn < 8; nn++) {                                \
                    asm volatile(                                               \
                        "mma.sync.aligned.m16n8k8.row.col.f32.tf32.tf32.f32 "   \
                        "{%0,%1,%2,%3}, {%4,%5,%6,%7}, {%8,%9}, {%0,%1,%2,%3};" \
                        : "+f"(acc[mm][nn][0]), "+f"(acc[mm][nn][1]),           \
                          "+f"(acc[mm][nn][2]), "+f"(acc[mm][nn][3])            \
                        : "r"(a[mm][0]), "r"(a[mm][1]), "r"(a[mm][2]), "r"(a[mm][3]), \
                          "r"(b[nn >> 1][(nn & 1) * 2]), "r"(b[nn >> 1][(nn & 1) * 2 + 1])); \
                }                                                               \
        }                                                                       \
    }

    // ---- prologue: fill 3 stages ----
    ISSUE_STAGE(0, 0);
    ISSUE_STAGE(1, 1);
    ISSUE_STAGE(2, 2);

    // ---- main loop ----
    // iter kc: wait for stage kc; sync; refill stage (kc+3)%4 (its last reader,
    // COMPUTE(kc-1), finished before this sync); compute kc.
#pragma unroll 1
    for (int kc = 0; kc < NCHUNK; kc++) {
        asm volatile("cp.async.wait_group 2;" ::: "memory");
        __syncthreads();
        if (kc + 3 < NCHUNK) { ISSUE_STAGE(kc + 3, (kc + 3) & 3); }
        COMPUTE(kc & 3);
    }

    // ---- epilogue: direct interleaved stores + bias ----
    {
        const float* bias_s = reinterpret_cast<const float*>(smem + SMEM_BIAS);
        const int r0 = lane >> 2;
        const int c0 = (lane & 3) * 2;
#pragma unroll
        for (int mm = 0; mm < 2; mm++) {
            const int mr = m0 + warp_m * 32 + mm * 16 + r0;
            float* yr0 = y + (size_t)mr * (DOUT * P_PART) + p;
            float* yr1 = yr0 + 8 * (DOUT * P_PART);
#pragma unroll
            for (int nn = 0; nn < 8; nn++) {
                const int n = warp_n * 64 + nn * 8 + c0;
                const float b0 = bias_s[n], b1 = bias_s[n + 1];
                const size_t o0 = (size_t)n * P_PART;
                yr0[o0]          = acc[mm][nn][0] + b0;
                yr0[o0 + P_PART] = acc[mm][nn][1] + b1;
                yr1[o0]          = acc[mm][nn][2] + b0;
                yr1[o0 + P_PART] = acc[mm][nn][3] + b1;
            }
        }
    }
}

extern "C" void kernel_launch(void* const* d_in, const int* in_sizes, int n_in,
                              void* d_out, int out_size)
{
    const float* x    = (const float*)d_in[0];
    const float* w    = (const float*)d_in[1];
    const float* bias = (const float*)d_in[2];
    float* y = (float*)d_out;

    int M = in_sizes[0] / (P_PART * DIN);      // 16384

    cudaFuncSetAttribute(diag_gemm_fused,
                         cudaFuncAttributeMaxDynamicSharedMemorySize, GEMM_SMEM);

    dim3 grid(P_PART, M / 128);                // p fastest
    diag_gemm_fused<<<grid, 512, GEMM_SMEM>>>(x, w, bias, y);
}

// round 10
// speedup vs baseline: 1.1210x; 1.0964x over previous
#include <cuda_runtime.h>
#include <cstdint>

// DiagLinear fused: y[m, n*16+p] = sum_k x[m, p*256+k] * w[p, n, k] + bias[n*16+p]
// P=16, DIN=DOUT=256, M=16384.
//
// TF32 mma.sync GEMM. CTA 256thr, tile M=128 x N=128, KC=32 x 8 chunks,
// 3-stage cp.async pipeline (96KB smem -> 2 CTAs/SM). Fragment double-buffering
// breaks ldmatrix->MMA serialization. W pre-rounded to tf32 (rna) in a 3us
// pre-kernel; X relies on HW truncation. Fused interleaved scatter stores
// (partition-partner CTAs adjacent in grid -> L2 line merge).

#define P_PART 16
#define DIN    256
#define DOUT   256
#define KC     32
#define NCHUNK 8
#define STAGES 3

#define ABUF_BYTES 16384                    // 128 rows x 128B
#define BBUF_BYTES 16384                    // 128 rows x 128B
#define SMEM_B_OFF (STAGES * ABUF_BYTES)    // 49152
#define SMEM_BIAS  (SMEM_B_OFF + STAGES * BBUF_BYTES)   // 98304
#define GEMM_SMEM  (SMEM_BIAS + 640)        // 98944

__device__ float g_wtf[(size_t)P_PART * DOUT * DIN];    // rna-rounded W, 4MB

static __device__ __forceinline__ uint32_t smem_u32(const void* p) {
    uint32_t a;
    asm("{ .reg .u64 t; cvta.to.shared.u64 t, %1; cvt.u32.u64 %0, t; }" : "=r"(a) : "l"(p));
    return a;
}

static __device__ __forceinline__ uint32_t f2tf32(float v) {
    uint32_t u;
    asm("cvt.rna.tf32.f32 %0, %1;" : "=r"(u) : "f"(v));
    return u;
}

static __device__ __forceinline__ void cp_async16(uint32_t dst, const void* src) {
    asm volatile("cp.async.cg.shared.global [%0], [%1], 16;" :: "r"(dst), "l"(src));
}

__global__ __launch_bounds__(256)
void round_w(const float* __restrict__ w)
{
    int i = blockIdx.x * 256 + threadIdx.x;
    g_wtf[i] = __uint_as_float(f2tf32(w[i]));
}

__global__ __launch_bounds__(256, 2)
void diag_gemm_fused(const float* __restrict__ x,
                     const float* __restrict__ bias, float* __restrict__ y)
{
    extern __shared__ char smem[];
    const int tid  = threadIdx.x;
    const int wid  = tid >> 5;
    const int lane = tid & 31;

    const int p     = blockIdx.x & 15;      // p fastest -> L2 write-merge
    const int nhalf = blockIdx.x >> 4;
    const int n0    = nhalf * 128;
    const int m0    = blockIdx.y * 128;

    const int warp_m = wid & 3;             // 0..3 -> 32 rows
    const int warp_n = wid >> 2;            // 0..1 -> 64 cols

    const float* xbase = x + (size_t)m0 * (P_PART * DIN) + (size_t)p * DIN;
    const float* wbase = g_wtf + (size_t)p * (DOUT * DIN) + (size_t)n0 * DIN;

    const uint32_t sbase = smem_u32(smem);

    {   // bias_s[i] = bias[(n0+i)*16 + p]
        float* bias_s = reinterpret_cast<float*>(smem + SMEM_BIAS);
        if (tid < 128) bias_s[tid] = bias[(n0 + tid) * P_PART + p];
    }

    // ---- per-lane ldmatrix addresses ----
    const int g  = lane >> 3;
    const int l8 = lane & 7;
    const int rowA = warp_m * 32 + (g & 1) * 8 + l8;
    const int cA   = g >> 1;
    const int rowB = warp_n * 64 + (g >> 1) * 8 + l8;
    const int cB   = g & 1;

    const uint32_t aAddr0 = sbase + rowA * 128;
    const uint32_t bAddr0 = sbase + SMEM_B_OFF + rowB * 128;
    const int swA = rowA & 7, swB = rowB & 7;

    // ---- cp.async: 4 x 16B for A, 4 x 16B for B per thread per stage ----
#define ISSUE_STAGE(KCI, ST)                                                    \
    {                                                                           \
        const int kofs = (KCI) * KC;                                            \
        _Pragma("unroll")                                                       \
        for (int i = 0; i < 4; i++) {                                           \
            int idx = i * 256 + tid;                                            \
            int row = idx >> 3, q = idx & 7;                                    \
            uint32_t so = row * 128 + ((q ^ (row & 7)) << 4);                   \
            cp_async16(sbase + (ST) * ABUF_BYTES + so,                          \
                       xbase + (size_t)row * (P_PART * DIN) + kofs + q * 4);    \
            cp_async16(sbase + SMEM_B_OFF + (ST) * BBUF_BYTES + so,             \
                       wbase + (size_t)row * DIN + kofs + q * 4);               \
        }                                                                       \
        asm volatile("cp.async.commit_group;" ::: "memory");                    \
    }

    float acc[2][8][4];
#pragma unroll
    for (int mm = 0; mm < 2; mm++)
#pragma unroll
        for (int nn = 0; nn < 8; nn++)
#pragma unroll
            for (int c = 0; c < 4; c++) acc[mm][nn][c] = 0.0f;

#define LD_FRAGS(SET, ABASE, BBASE, KS)                                         \
    {                                                                           \
        const int cb = (KS) * 2;                                                \
        _Pragma("unroll")                                                       \
        for (int mm = 0; mm < 2; mm++) {                                        \
            uint32_t ad = (ABASE) + mm * 2048 + (((cb + cA) ^ swA) << 4);       \
            asm volatile(                                                       \
                "ldmatrix.sync.aligned.m8n8.x4.shared.b16 {%0,%1,%2,%3}, [%4];" \
                : "=r"(a[SET][mm][0]), "=r"(a[SET][mm][1]),                     \
                  "=r"(a[SET][mm][2]), "=r"(a[SET][mm][3])                      \
                : "r"(ad));                                                     \
        }                                                                       \
        _Pragma("unroll")                                                       \
        for (int q = 0; q < 4; q++) {                                           \
            uint32_t bd = (BBASE) + q * 2048 + (((cb + cB) ^ swB) << 4);        \
            asm volatile(                                                       \
                "ldmatrix.sync.aligned.m8n8.x4.shared.b16 {%0,%1,%2,%3}, [%4];" \
                : "=r"(b[SET][q][0]), "=r"(b[SET][q][1]),                       \
                  "=r"(b[SET][q][2]), "=r"(b[SET][q][3])                        \
                : "r"(bd));                                                     \
        }                                                                       \
    }

#define MMA_SET(SET)                                                            \
    _Pragma("unroll")                                                           \
    for (int mm = 0; mm < 2; mm++)                                              \
        _Pragma("unroll")                                                       \
        for (int nn = 0; nn < 8; nn++) {                                        \
            asm volatile(                                                       \
                "mma.sync.aligned.m16n8k8.row.col.f32.tf32.tf32.f32 "           \
                "{%0,%1,%2,%3}, {%4,%5,%6,%7}, {%8,%9}, {%0,%1,%2,%3};"         \
                : "+f"(acc[mm][nn][0]), "+f"(acc[mm][nn][1]),                   \
                  "+f"(acc[mm][nn][2]), "+f"(acc[mm][nn][3])                    \
                : "r"(a[SET][mm][0]), "r"(a[SET][mm][1]),                       \
                  "r"(a[SET][mm][2]), "r"(a[SET][mm][3]),                       \
                  "r"(b[SET][nn >> 1][(nn & 1) * 2]),                           \
                  "r"(b[SET][nn >> 1][(nn & 1) * 2 + 1]));                      \
        }

#define COMPUTE(BUF)                                                            \
    {                                                                           \
        const uint32_t abase = aAddr0 + (BUF) * ABUF_BYTES;                     \
        const uint32_t bbase = bAddr0 + (BUF) * BBUF_BYTES;                     \
        uint32_t a[2][2][4], b[2][4][4];                                        \
        LD_FRAGS(0, abase, bbase, 0);                                           \
        LD_FRAGS(1, abase, bbase, 1);                                           \
        MMA_SET(0);                                                             \
        LD_FRAGS(0, abase, bbase, 2);                                           \
        MMA_SET(1);                                                             \
        LD_FRAGS(1, abase, bbase, 3);                                           \
        MMA_SET(0);                                                             \
        MMA_SET(1);                                                             \
    }

    // ---- prologue: 2 stages in flight ----
    ISSUE_STAGE(0, 0);
    ISSUE_STAGE(1, 1);

    // ---- main loop: wait stage kc; sync; refill stage kc+2 (buf freed at
    //      iter kc-1); compute kc. One sync per iteration. ----
#pragma unroll 1
    for (int kc = 0; kc < NCHUNK; kc++) {
        asm volatile("cp.async.wait_group 1;" ::: "memory");
        __syncthreads();
        if (kc + 2 < NCHUNK) {
            const int st = (kc + 2) % 3;
            ISSUE_STAGE(kc + 2, st);
        }
        COMPUTE(kc % 3);
    }

    // ---- epilogue: direct interleaved stores + bias ----
    {
        const float* bias_s = reinterpret_cast<const float*>(smem + SMEM_BIAS);
        const int r0 = lane >> 2;
        const int c0 = (lane & 3) * 2;
#pragma unroll
        for (int mm = 0; mm < 2; mm++) {
            const int mr = m0 + warp_m * 32 + mm * 16 + r0;
            float* yr0 = y + (size_t)mr * (DOUT * P_PART) + p;
            float* yr1 = yr0 + 8 * (DOUT * P_PART);
#pragma unroll
            for (int nn = 0; nn < 8; nn++) {
                const int nl = warp_n * 64 + nn * 8 + c0;      // local n
                const float b0 = bias_s[nl], b1 = bias_s[nl + 1];
                const size_t o0 = (size_t)(n0 + nl) * P_PART;
                yr0[o0]          = acc[mm][nn][0] + b0;
                yr0[o0 + P_PART] = acc[mm][nn][1] + b1;
                yr1[o0]          = acc[mm][nn][2] + b0;
                yr1[o0 + P_PART] = acc[mm][nn][3] + b1;
            }
        }
    }
}

extern "C" void kernel_launch(void* const* d_in, const int* in_sizes, int n_in,
                              void* d_out, int out_size)
{
    const float* x    = (const float*)d_in[0];
    const float* w    = (const float*)d_in[1];
    const float* bias = (const float*)d_in[2];
    float* y = (float*)d_out;

    int M = in_sizes[0] / (P_PART * DIN);      // 16384

    cudaFuncSetAttribute(diag_gemm_fused,
                         cudaFuncAttributeMaxDynamicSharedMemorySize, GEMM_SMEM);

    round_w<<<(P_PART * DOUT * DIN) / 256, 256>>>(w);

    dim3 grid(32, M / 128);                    // x: p(16) * nhalf(2), p fastest
    diag_gemm_fused<<<grid, 256, GEMM_SMEM>>>(x, bias, y);
}

// round 11
// speedup vs baseline: 2.0653x; 1.8423x over previous
#include <cuda_runtime.h>
#include <cstdint>

// DiagLinear, two-phase:
//   K1 diag_gemm: per-partition TF32 mma.sync GEMM -> scratch ytmp[m][p][n]
//      (contiguous stores; bias folded in). CTA 256thr, tile M128xN128,
//      3-stage cp.async, 2 CTAs/SM, frag double-buffering, W pre-rounded rna.
//   K2 permute_out: ytmp[m][p][n] -> y[m][n*16+p], coalesced both sides,
//      33KB smem -> 6 CTAs/SM.

#define P_PART 16
#define DIN    256
#define DOUT   256
#define MROWS  16384
#define KC     32
#define NCHUNK 8
#define STAGES 3

#define ABUF_BYTES 16384
#define BBUF_BYTES 16384
#define SMEM_B_OFF (STAGES * ABUF_BYTES)                // 49152
#define SMEM_BIAS  (SMEM_B_OFF + STAGES * BBUF_BYTES)   // 98304
#define GEMM_SMEM  (SMEM_BIAS + 640)                    // 98944

#define NPAD 260

__device__ float g_wtf[(size_t)P_PART * DOUT * DIN];        // rna W, 4MB
__device__ float g_ytmp[(size_t)MROWS * P_PART * DOUT];     // [m][p][n], 256MB

static __device__ __forceinline__ uint32_t smem_u32(const void* p) {
    uint32_t a;
    asm("{ .reg .u64 t; cvta.to.shared.u64 t, %1; cvt.u32.u64 %0, t; }" : "=r"(a) : "l"(p));
    return a;
}

static __device__ __forceinline__ uint32_t f2tf32(float v) {
    uint32_t u;
    asm("cvt.rna.tf32.f32 %0, %1;" : "=r"(u) : "f"(v));
    return u;
}

static __device__ __forceinline__ void cp_async16(uint32_t dst, const void* src) {
    asm volatile("cp.async.cg.shared.global [%0], [%1], 16;" :: "r"(dst), "l"(src));
}

__global__ __launch_bounds__(256)
void round_w(const float* __restrict__ w)
{
    int i = blockIdx.x * 256 + threadIdx.x;
    g_wtf[i] = __uint_as_float(f2tf32(w[i]));
}

__global__ __launch_bounds__(256, 2)
void diag_gemm(const float* __restrict__ x, const float* __restrict__ bias)
{
    extern __shared__ char smem[];
    const int tid  = threadIdx.x;
    const int wid  = tid >> 5;
    const int lane = tid & 31;

    const int p     = blockIdx.x & 15;      // p fastest -> W shared across m-wave in L2
    const int nhalf = blockIdx.x >> 4;
    const int n0    = nhalf * 128;
    const int m0    = blockIdx.y * 128;

    const int warp_m = wid & 3;
    const int warp_n = wid >> 2;

    const float* xbase = x + (size_t)m0 * (P_PART * DIN) + (size_t)p * DIN;
    const float* wbase = g_wtf + (size_t)p * (DOUT * DIN) + (size_t)n0 * DIN;

    const uint32_t sbase = smem_u32(smem);

    {   // bias_s[i] = bias[(n0+i)*16 + p]
        float* bias_s = reinterpret_cast<float*>(smem + SMEM_BIAS);
        if (tid < 128) bias_s[tid] = bias[(n0 + tid) * P_PART + p];
    }

    const int g  = lane >> 3;
    const int l8 = lane & 7;
    const int rowA = warp_m * 32 + (g & 1) * 8 + l8;
    const int cA   = g >> 1;
    const int rowB = warp_n * 64 + (g >> 1) * 8 + l8;
    const int cB   = g & 1;

    const uint32_t aAddr0 = sbase + rowA * 128;
    const uint32_t bAddr0 = sbase + SMEM_B_OFF + rowB * 128;
    const int swA = rowA & 7, swB = rowB & 7;

#define ISSUE_STAGE(KCI, ST)                                                    \
    {                                                                           \
        const int kofs = (KCI) * KC;                                            \
        _Pragma("unroll")                                                       \
        for (int i = 0; i < 4; i++) {                                           \
            int idx = i * 256 + tid;                                            \
            int row = idx >> 3, q = idx & 7;                                    \
            uint32_t so = row * 128 + ((q ^ (row & 7)) << 4);                   \
            cp_async16(sbase + (ST) * ABUF_BYTES + so,                          \
                       xbase + (size_t)row * (P_PART * DIN) + kofs + q * 4);    \
            cp_async16(sbase + SMEM_B_OFF + (ST) * BBUF_BYTES + so,             \
                       wbase + (size_t)row * DIN + kofs + q * 4);               \
        }                                                                       \
        asm volatile("cp.async.commit_group;" ::: "memory");                    \
    }

    float acc[2][8][4];
#pragma unroll
    for (int mm = 0; mm < 2; mm++)
#pragma unroll
        for (int nn = 0; nn < 8; nn++)
#pragma unroll
            for (int c = 0; c < 4; c++) acc[mm][nn][c] = 0.0f;

#define LD_FRAGS(SET, ABASE, BBASE, KS)                                         \
    {                                                                           \
        const int cb = (KS) * 2;                                                \
        _Pragma("unroll")                                                       \
        for (int mm = 0; mm < 2; mm++) {                                        \
            uint32_t ad = (ABASE) + mm * 2048 + (((cb + cA) ^ swA) << 4);       \
            asm volatile(                                                       \
                "ldmatrix.sync.aligned.m8n8.x4.shared.b16 {%0,%1,%2,%3}, [%4];" \
                : "=r"(a[SET][mm][0]), "=r"(a[SET][mm][1]),                     \
                  "=r"(a[SET][mm][2]), "=r"(a[SET][mm][3])                      \
                : "r"(ad));                                                     \
        }                                                                       \
        _Pragma("unroll")                                                       \
        for (int q = 0; q < 4; q++) {                                           \
            uint32_t bd = (BBASE) + q * 2048 + (((cb + cB) ^ swB) << 4);        \
            asm volatile(                                                       \
                "ldmatrix.sync.aligned.m8n8.x4.shared.b16 {%0,%1,%2,%3}, [%4];" \
                : "=r"(b[SET][q][0]), "=r"(b[SET][q][1]),                       \
                  "=r"(b[SET][q][2]), "=r"(b[SET][q][3])                        \
                : "r"(bd));                                                     \
        }                                                                       \
    }

#define MMA_SET(SET)                                                            \
    _Pragma("unroll")                                                           \
    for (int mm = 0; mm < 2; mm++)                                              \
        _Pragma("unroll")                                                       \
        for (int nn = 0; nn < 8; nn++) {                                        \
            asm volatile(                                                       \
                "mma.sync.aligned.m16n8k8.row.col.f32.tf32.tf32.f32 "           \
                "{%0,%1,%2,%3}, {%4,%5,%6,%7}, {%8,%9}, {%0,%1,%2,%3};"         \
                : "+f"(acc[mm][nn][0]), "+f"(acc[mm][nn][1]),                   \
                  "+f"(acc[mm][nn][2]), "+f"(acc[mm][nn][3])                    \
                : "r"(a[SET][mm][0]), "r"(a[SET][mm][1]),                       \
                  "r"(a[SET][mm][2]), "r"(a[SET][mm][3]),                       \
                  "r"(b[SET][nn >> 1][(nn & 1) * 2]),                           \
                  "r"(b[SET][nn >> 1][(nn & 1) * 2 + 1]));                      \
        }

#define COMPUTE(BUF)                                                            \
    {                                                                           \
        const uint32_t abase = aAddr0 + (BUF) * ABUF_BYTES;                     \
        const uint32_t bbase = bAddr0 + (BUF) * BBUF_BYTES;                     \
        uint32_t a[2][2][4], b[2][4][4];                                        \
        LD_FRAGS(0, abase, bbase, 0);                                           \
        LD_FRAGS(1, abase, bbase, 1);                                           \
        MMA_SET(0);                                                             \
        LD_FRAGS(0, abase, bbase, 2);                                           \
        MMA_SET(1);                                                             \
        LD_FRAGS(1, abase, bbase, 3);                                           \
        MMA_SET(0);                                                             \
        MMA_SET(1);                                                             \
    }

    ISSUE_STAGE(0, 0);
    ISSUE_STAGE(1, 1);

#pragma unroll 1
    for (int kc = 0; kc < NCHUNK; kc++) {
        asm volatile("cp.async.wait_group 1;" ::: "memory");
        __syncthreads();
        if (kc + 2 < NCHUNK) {
            const int st = (kc + 2) % 3;
            ISSUE_STAGE(kc + 2, st);
        }
        COMPUTE(kc % 3);
    }

    // ---- epilogue: contiguous stores to ytmp[m][p][n] (+bias) ----
    {
        const float* bias_s = reinterpret_cast<const float*>(smem + SMEM_BIAS);
        const int r0 = lane >> 2;
        const int c0 = (lane & 3) * 2;
#pragma unroll
        for (int mm = 0; mm < 2; mm++) {
            const int mr = m0 + warp_m * 32 + mm * 16 + r0;
            float* yt0 = g_ytmp + ((size_t)mr * P_PART + p) * DOUT + n0;
            float* yt1 = yt0 + (size_t)8 * P_PART * DOUT;
#pragma unroll
            for (int nn = 0; nn < 8; nn++) {
                const int nl = warp_n * 64 + nn * 8 + c0;
                const float b0 = bias_s[nl], b1 = bias_s[nl + 1];
                *reinterpret_cast<float2*>(yt0 + nl) =
                    make_float2(acc[mm][nn][0] + b0, acc[mm][nn][1] + b1);
                *reinterpret_cast<float2*>(yt1 + nl) =
                    make_float2(acc[mm][nn][2] + b0, acc[mm][nn][3] + b1);
            }
        }
    }
}

// ---- K2: permute ytmp[m][p][n] -> y[m][n*16+p] ----
__global__ __launch_bounds__(256)
void permute_out(float* __restrict__ y)
{
    __shared__ float ts[2][P_PART * NPAD];
    const int tid = threadIdx.x;
    const int mb  = blockIdx.x * 2;

    const float* src = g_ytmp + (size_t)mb * (P_PART * DOUT);
#pragma unroll
    for (int m = 0; m < 2; m++) {
#pragma unroll
        for (int i = 0; i < 4; i++) {
            int idx = i * 256 + tid;            // float4 index 0..1023
            int pp  = idx >> 6;
            int n4  = idx & 63;
            float4 v = *reinterpret_cast<const float4*>(
                src + (size_t)m * (P_PART * DOUT) + pp * DOUT + n4 * 4);
            *reinterpret_cast<float4*>(&ts[m][pp * NPAD + n4 * 4]) = v;
        }
    }
    __syncthreads();

#pragma unroll
    for (int m = 0; m < 2; m++) {
        float* yrow = y + (size_t)(mb + m) * (DOUT * P_PART);
#pragma unroll
        for (int i = 0; i < 4; i++) {
            int o  = (i * 256 + tid) * 4;
            int pb = o & 15;
            int n  = o >> 4;
            float4 r;
            r.x = ts[m][(pb + 0) * NPAD + n];
            r.y = ts[m][(pb + 1) * NPAD + n];
            r.z = ts[m][(pb + 2) * NPAD + n];
            r.w = ts[m][(pb + 3) * NPAD + n];
            *reinterpret_cast<float4*>(yrow + o) = r;
        }
    }
}

extern "C" void kernel_launch(void* const* d_in, const int* in_sizes, int n_in,
                              void* d_out, int out_size)
{
    const float* x    = (const float*)d_in[0];
    const float* w    = (const float*)d_in[1];
    const float* bias = (const float*)d_in[2];
    float* y = (float*)d_out;

    int M = in_sizes[0] / (P_PART * DIN);      // 16384

    cudaFuncSetAttribute(diag_gemm,
                         cudaFuncAttributeMaxDynamicSharedMemorySize, GEMM_SMEM);

    round_w<<<(P_PART * DOUT * DIN) / 256, 256>>>(w);
    diag_gemm<<<dim3(32, M / 128), 256, GEMM_SMEM>>>(x, bias);
    permute_out<<<M / 2, 256>>>(y);
}